// round 17
// baseline (speedup 1.0000x reference)
#include <cuda_runtime.h>
#include <cuda_bf16.h>
#include <math.h>
#include <stdint.h>

#define BB 128
#define TT 1024
#define DD 43
#define HH 256
#define G4 1024

// ---- static device scratch (allocation-free) ----
__device__ float    g_xg[(size_t)TT * BB * G4];   // [t][b][g]
__device__ float    g_hs[(size_t)BB * TT * HH];   // [b][t][k]
__device__ float    g_a1[(size_t)BB * TT * HH];   // [tok][k]
__device__ uint16_t g_hhi[2 * 16 * 256 * 8];      // [t&1][bg][k][b] bf16 hi
__device__ uint16_t g_hlo[2 * 16 * 256 * 8];      // [t&1][bg][k][b] bf16 lo
__device__ int      g_flag2[16 * 8 * 8 * 64];     // [bg][producer][consumer], 256B pad

__device__ __forceinline__ int ld_acquire(const int* p) {
    int v;
    asm volatile("ld.acquire.gpu.global.b32 %0, [%1];" : "=r"(v) : "l"(p));
    return v;
}
__device__ __forceinline__ void st_release(int* p, int v) {
    asm volatile("st.release.gpu.global.b32 [%0], %1;" :: "l"(p), "r"(v) : "memory");
}
__device__ __forceinline__ float sigf(float x) {
    float y;
    asm("tanh.approx.f32 %0, %1;" : "=f"(y) : "f"(0.5f * x));
    return 0.5f * y + 0.5f;
}
__device__ __forceinline__ float tanhf_fast(float x) {
    float y;
    asm("tanh.approx.f32 %0, %1;" : "=f"(y) : "f"(x));
    return y;
}
__device__ __forceinline__ uint32_t smem_u32(const void* p) {
    uint32_t a;
    asm("{ .reg .u64 t; cvta.to.shared.u64 t, %1; cvt.u32.u64 %0, t; }" : "=r"(a) : "l"(p));
    return a;
}

#define LDSM4(r0, r1, r2, r3, addr) \
    asm volatile("ldmatrix.sync.aligned.m8n8.x4.shared.b16 {%0,%1,%2,%3}, [%4];" \
                 : "=r"(r0), "=r"(r1), "=r"(r2), "=r"(r3) : "r"(addr))
#define LDSM2T(r0, r1, addr) \
    asm volatile("ldmatrix.sync.aligned.m8n8.x2.trans.shared.b16 {%0,%1}, [%2];" \
                 : "=r"(r0), "=r"(r1) : "r"(addr))
#define MMA_BF16(c0, c1, c2, c3, a0, a1, a2, a3, b0, b1) \
    asm volatile("mma.sync.aligned.m16n8k16.row.col.f32.bf16.bf16.f32 " \
                 "{%0,%1,%2,%3}, {%4,%5,%6,%7}, {%8,%9}, {%0,%1,%2,%3};" \
                 : "+f"(c0), "+f"(c1), "+f"(c2), "+f"(c3) \
                 : "r"(a0), "r"(a1), "r"(a2), "r"(a3), "r"(b0), "r"(b1))

// ---------------------------------------------------------------------------
__global__ void k_init() {
    int i = blockIdx.x * 256 + threadIdx.x;
    if (i < 1024) g_flag2[i * 64] = 0;
}

// ---------------------------------------------------------------------------
// Kernel A: xg[t][b][g] = xin[b,t,:] . W_ih[g,:] + b_ih[g] + b_hh[g]
// ---------------------------------------------------------------------------
__global__ void __launch_bounds__(256) kA(const float* __restrict__ x,
                                          const float* __restrict__ Wih,
                                          const float* __restrict__ bih,
                                          const float* __restrict__ bhh) {
    __shared__ float xin[32 * 44];
    const int tid = threadIdx.x;
    const int g0  = blockIdx.x * 256;
    const int t0  = blockIdx.y * 32;
    const int b   = blockIdx.z;

    for (int e = tid; e < 32 * 44; e += 256) {
        int tt = e / 44, d = e % 44;
        int t = t0 + tt;
        float v = 0.0f;
        if (d < 35)      v = x[((size_t)b * TT + t) * DD + d];
        else if (d < 43) { if (t > 0) v = x[((size_t)b * TT + t - 1) * DD + d]; }
        xin[e] = v;
    }

    const int g = g0 + tid;
    float w[44];
#pragma unroll
    for (int d = 0; d < 43; d++) w[d] = Wih[g * DD + d];
    w[43] = 0.0f;
    const float bias = bih[g] + bhh[g];
    __syncthreads();

#pragma unroll 4
    for (int tt = 0; tt < 32; tt++) {
        const float* xr = &xin[tt * 44];
        float acc = bias;
#pragma unroll
        for (int d = 0; d < 44; d++) acc += w[d] * xr[d];
        g_xg[((size_t)(t0 + tt) * BB + b) * G4 + g] = acc;
    }
}

// ---------------------------------------------------------------------------
// Kernel B: persistent LSTM, 128 CTAs = 16 batch-groups x 8 hidden-slices.
// HMMA gate GEMM (bf16 hi/lo 3-product, fp32 acc). Exchange: parity
// double-buffered bf16 planes in L2 + private per-consumer flag lines.
// ---------------------------------------------------------------------------
#define WS      528                    // W row stride, bytes
#define WHI_OFF 0                      // 67584 B
#define WLO_OFF 67584                  // 67584 B
#define BHI_OFF 135168                 // 4096 B
#define BLO_OFF 139264                 // 4096 B
#define GSH_OFF 143360                 // 2*1280 floats = 10240 B
#define SMEM_B  153600

__global__ void __launch_bounds__(512, 1) kB(const float* __restrict__ Whh) {
    extern __shared__ char smc[];
    float* gsh = (float*)(smc + GSH_OFF);   // [2 half][128 r][10]

    const int tid  = threadIdx.x;
    const int wid  = tid >> 5;
    const int lane = tid & 31;
    const int cta = blockIdx.x;
    const int bg  = cta >> 3;          // batch group 0..15
    const int hsl = cta & 7;           // hidden slice 0..7
    const int b0  = bg * 8;

    const uint32_t smb = smem_u32(smc);

    // ---- W hi/lo preload: row r, col k at byte r*WS + k*2 ----
    for (int idx = tid; idx < 128 * 256; idx += 512) {
        int r = idx >> 8, k = idx & 255;
        int R = (r & 3) * 256 + hsl * 32 + (r >> 2);
        float w = Whh[R * 256 + k];
        __nv_bfloat16 hi = __float2bfloat16(w);
        __nv_bfloat16 lo = __float2bfloat16(w - __bfloat162float(hi));
        *(__nv_bfloat16*)(smc + WHI_OFF + r * WS + k * 2) = hi;
        *(__nv_bfloat16*)(smc + WLO_OFF + r * WS + k * 2) = lo;
    }
    // zero h planes (h(-1) = 0): 2 x 4096 B contiguous
    for (int e = tid; e < 2048; e += 512)
        ((uint32_t*)(smc + BHI_OFF))[e] = 0u;
    __syncthreads();

    // role mappings
    const int q  = tid >> 6;           // stage group / producer slice 0..7
    const int qt = tid & 63;
    const int sp = qt >> 5;            // plane 0 = hi, 1 = lo  (stage)
    const int skk = qt & 31;           // k within slice        (stage)
    const int ub = (tid >> 5) & 7;     // batch (pointwise, tid<256)
    const int uk = tid & 31;           // local k (pointwise)

    // MMA mapping: row tile rt = wid>>1 (16 rows), K-half khm = wid&1 (128 K)
    const int rt  = wid >> 1;
    const int khm = wid & 1;
    const int arow  = rt * 16 + ((lane >> 3) & 1) * 8 + (lane & 7);
    const int acol8 = (lane >> 4) * 8;
    const uint32_t aHi = smb + WHI_OFF + arow * WS + (khm * 128 + acol8) * 2;
    const uint32_t aLo = smb + WLO_OFF + arow * WS + (khm * 128 + acol8) * 2;
    const uint32_t bHi = smb + BHI_OFF + (khm * 128 + (lane & 15)) * 16;
    const uint32_t bLo = smb + BLO_OFF + (khm * 128 + (lane & 15)) * 16;
    const int dg = lane >> 2, dt = lane & 3;    // D frag coords

    // flag addressing: poll g_flag2[bg][q][hsl]; release g_flag2[bg][hsl][c]
    const int* pollp = &g_flag2[((bg * 8 + q) * 8 + hsl) * 64];
    int*       relbase = &g_flag2[(bg * 8 + hsl) * 8 * 64];

    float c0s = 0.0f;

    // prefetch xg[0]
    float px0, px1, px2, px3;
    if (tid < 256) {
        const float* p = &g_xg[((size_t)b0 + ub) * G4 + hsl * 32 + uk];
        px0 = __ldcg(p);       px1 = __ldcg(p + 256);
        px2 = __ldcg(p + 512); px3 = __ldcg(p + 768);
    }

    for (int t = 0; t < TT; t++) {
        // prefetch next step's xg
        float nx0, nx1, nx2, nx3;
        if (tid < 256) {
            int tn = (t + 1 < TT) ? (t + 1) : t;
            const float* p = &g_xg[((size_t)tn * BB + b0 + ub) * G4 + hsl * 32 + uk];
            nx0 = __ldcg(p);       nx1 = __ldcg(p + 256);
            nx2 = __ldcg(p + 512); nx3 = __ldcg(p + 768);
        }

        // ---- stage remote slices: private flag poll + bf16 16B row copy ----
        // h(t-1) lives in parity buffer (t-1)&1 = (t+1)&1.
        if (t > 0 && q != hsl) {
            if (qt == 0) {
                while (ld_acquire(pollp) < t) { }
            }
            asm volatile("bar.sync %0, 64;" :: "r"(1 + q) : "memory");
            {
                int k = q * 32 + skk;
                size_t sidx = (((size_t)((t + 1) & 1) * 16 + bg) * 256 + k) * 8;
                const uint16_t* src = sp ? &g_hlo[sidx] : &g_hhi[sidx];
                uint4 v;
                asm volatile("ld.global.cg.v4.u32 {%0,%1,%2,%3}, [%4];"
                             : "=r"(v.x), "=r"(v.y), "=r"(v.z), "=r"(v.w)
                             : "l"(src));
                char* dst = smc + (sp ? BLO_OFF : BHI_OFF) + k * 16;
                *(uint4*)dst = v;
            }
        }
        __syncthreads();   // B complete (stage + own-slice writes from t-1)

        // ---- HMMA: 8 K-chunks x 3 products, fp32 accumulate ----
        {
            float c0 = 0.f, c1 = 0.f, c2 = 0.f, c3 = 0.f;
#pragma unroll
            for (int kc = 0; kc < 8; kc++) {
                uint32_t ah0, ah1, ah2, ah3, al0, al1, al2, al3;
                uint32_t bh0, bh1, bl0, bl1;
                LDSM4(ah0, ah1, ah2, ah3, aHi + kc * 32);
                LDSM4(al0, al1, al2, al3, aLo + kc * 32);
                LDSM2T(bh0, bh1, bHi + kc * 256);
                LDSM2T(bl0, bl1, bLo + kc * 256);
                MMA_BF16(c0, c1, c2, c3, ah0, ah1, ah2, ah3, bh0, bh1);
                MMA_BF16(c0, c1, c2, c3, ah0, ah1, ah2, ah3, bl0, bl1);
                MMA_BF16(c0, c1, c2, c3, al0, al1, al2, al3, bh0, bh1);
            }
            float* gp = &gsh[khm * 1280 + (rt * 16 + dg) * 10 + dt * 2];
            *(float2*)gp        = make_float2(c0, c1);
            *(float2*)(gp + 80) = make_float2(c2, c3);   // row +8
        }
        __syncthreads();   // gates in gsh

        // ---- pointwise LSTM update (tid < 256) ----
        if (tid < 256) {
            const int o = (uk * 4) * 10 + ub;
            float gi = sigf(      px0 + gsh[o]      + gsh[1280 + o]);
            float gf = sigf(      px1 + gsh[o + 10] + gsh[1290 + o]);
            float gg = tanhf_fast(px2 + gsh[o + 20] + gsh[1300 + o]);
            float go = sigf(      px3 + gsh[o + 30] + gsh[1310 + o]);
            c0s = gf * c0s + gi * gg;
            float h = go * tanhf_fast(c0s);
            g_hs[(((size_t)(b0 + ub)) * TT + t) * HH + hsl * 32 + uk] = h;
            int k = hsl * 32 + uk;
            __nv_bfloat16 hi = __float2bfloat16(h);
            __nv_bfloat16 lo = __float2bfloat16(h - __bfloat162float(hi));
            // own slice -> local B planes
            int off = (k * 8 + ub) * 2;
            *(__nv_bfloat16*)(smc + BHI_OFF + off) = hi;
            *(__nv_bfloat16*)(smc + BLO_OFF + off) = lo;
            // publish bf16 planes for peers (parity buffer t&1)
            if (t + 1 < TT) {
                size_t didx = (((size_t)(t & 1) * 16 + bg) * 256 + k) * 8 + ub;
                g_hhi[didx] = *(uint16_t*)&hi;
                g_hlo[didx] = *(uint16_t*)&lo;
            }
            px0 = nx0; px1 = nx1; px2 = nx2; px3 = nx3;
            asm volatile("bar.sync 9, 256;" ::: "memory");   // h stores done
            if (tid == 0 && t + 1 < TT) {
#pragma unroll
                for (int c = 0; c < 8; c++)
                    if (c != hsl) st_release(relbase + c * 64, t + 1);
            }
        }
    }
}

// ---------------------------------------------------------------------------
// Kernel C1: a1 = relu(hs @ W_afc1^T + b).  Block: 32 tokens x 256 outputs.
// ---------------------------------------------------------------------------
#define SMEM_C1 ((32 * 256 + 256 * 68) * 4)

__global__ void __launch_bounds__(256) kC1(const float* __restrict__ Wa,
                                           const float* __restrict__ ba) {
    extern __shared__ float sm[];
    float* hsh = sm;               // [32][256]
    float* Ws  = sm + 32 * 256;    // [256][68] current K-chunk

    const int tid  = threadIdx.x;
    const int tok0 = blockIdx.x * 32;

    for (int e = tid; e < 32 * 256; e += 256)
        hsh[e] = g_hs[(size_t)tok0 * 256 + e];

    float acc[32];
    const float bias = ba[tid];
#pragma unroll
    for (int i = 0; i < 32; i++) acc[i] = bias;

    for (int kc = 0; kc < 4; kc++) {
        __syncthreads();
        for (int e = tid; e < 256 * 64; e += 256) {
            int j = e >> 6, kk = e & 63;
            Ws[j * 68 + kk] = Wa[j * 256 + kc * 64 + kk];
        }
        __syncthreads();
        const float4* wp = (const float4*)&Ws[tid * 68];
#pragma unroll
        for (int q = 0; q < 16; q++) {
            float4 w4 = wp[q];
            const int kbase = kc * 64 + q * 4;
#pragma unroll 8
            for (int tt = 0; tt < 32; tt++) {
                float4 h = *(const float4*)&hsh[tt * 256 + kbase];
                acc[tt] += w4.x * h.x + w4.y * h.y + w4.z * h.z + w4.w * h.w;
            }
        }
    }
#pragma unroll
    for (int tt = 0; tt < 32; tt++)
        g_a1[((size_t)(tok0 + tt)) * 256 + tid] = fmaxf(acc[tt], 0.0f);
}

// ---------------------------------------------------------------------------
// Kernel C2: cont / bin / act heads.
// ---------------------------------------------------------------------------
#define CONT_BASE 0
#define BIN_BASE  (128 * 1024 * 50)
#define ACT_BASE  (BIN_BASE + 128 * 1024 * 10)
#define SMEM_C2 ((32 * 268 + 32 * 256 + 50 * 268 + 10 * 268 + 8 * 256 + 68) * 4)

__global__ void __launch_bounds__(256) kC2(const float* __restrict__ x,
                                           const float* __restrict__ Wao,
                                           const float* __restrict__ bao,
                                           const float* __restrict__ Wc,
                                           const float* __restrict__ bc,
                                           const float* __restrict__ Wb,
                                           const float* __restrict__ bb,
                                           float* __restrict__ out) {
    extern __shared__ float sm[];
    float* pred = sm;                   // [32][268]  (h | cur)
    float* a1s  = pred + 32 * 268;      // [32][256]
    float* Wcs  = a1s  + 32 * 256;      // [50][268]
    float* Wbs  = Wcs  + 50 * 268;      // [10][268]
    float* Was  = Wbs  + 10 * 268;      // [8][256]
    float* bcs  = Was  + 8 * 256;       // 50
    float* bbs  = bcs + 50;             // 10
    float* bas  = bbs + 10;             // 8

    const int tid  = threadIdx.x;
    const int tok0 = blockIdx.x * 32;

    for (int e = tid; e < 32 * 256; e += 256) {
        int tt = e >> 8, k = e & 255;
        pred[tt * 268 + k] = g_hs[(size_t)tok0 * 256 + e];
        a1s[e]             = g_a1[(size_t)tok0 * 256 + e];
    }
    if (tid < 32 * 8) {
        int tt = tid >> 3, j = tid & 7;
        pred[tt * 268 + 256 + j] = x[((size_t)(tok0 + tt)) * DD + 35 + j];
    }
    for (int e = tid; e < 50 * 264; e += 256) {
        int o = e / 264, d = e % 264;
        Wcs[o * 268 + d] = Wc[e];
    }
    for (int e = tid; e < 10 * 264; e += 256) {
        int o = e / 264, d = e % 264;
        Wbs[o * 268 + d] = Wb[e];
    }
    for (int e = tid; e < 8 * 256; e += 256) Was[e] = Wao[e];
    if (tid < 50) bcs[tid] = bc[tid];
    if (tid < 10) bbs[tid] = bb[tid];
    if (tid < 8)  bas[tid] = bao[tid];
    __syncthreads();

    for (int idx = tid; idx < 32 * 68; idx += 256) {
        const int tt   = idx / 68;
        const int o    = idx % 68;
        const int gtok = tok0 + tt;
        if (o < 50) {
            float acc = bcs[o];
            const float4* wp = (const float4*)&Wcs[o * 268];
            const float4* pp = (const float4*)&pred[tt * 268];
#pragma unroll 11
            for (int q = 0; q < 66; q++) {
                float4 w = wp[q], p = pp[q];
                acc += w.x * p.x + w.y * p.y + w.z * p.z + w.w * p.w;
            }
            out[CONT_BASE + (size_t)gtok * 50 + o] = acc;
        } else if (o < 60) {
            const int o2 = o - 50;
            float acc = bbs[o2];
            const float4* wp = (const float4*)&Wbs[o2 * 268];
            const float4* pp = (const float4*)&pred[tt * 268];
#pragma unroll 11
            for (int q = 0; q < 66; q++) {
                float4 w = wp[q], p = pp[q];
                acc += w.x * p.x + w.y * p.y + w.z * p.z + w.w * p.w;
            }
            out[BIN_BASE + (size_t)gtok * 10 + o2] = 1.0f / (1.0f + __expf(-acc));
        } else {
            const int o3 = o - 60;
            float acc = bas[o3];
            const float4* wp = (const float4*)&Was[o3 * 256];
            const float4* pp = (const float4*)&a1s[tt * 256];
#pragma unroll 16
            for (int q = 0; q < 64; q++) {
                float4 w = wp[q], p = pp[q];
                acc += w.x * p.x + w.y * p.y + w.z * p.z + w.w * p.w;
            }
            out[ACT_BASE + (size_t)gtok * 8 + o3] = acc;
        }
    }
}

// ---------------------------------------------------------------------------
extern "C" void kernel_launch(void* const* d_in, const int* in_sizes, int n_in,
                              void* d_out, int out_size) {
    const float* x    = (const float*)d_in[0];
    const float* Wih  = (const float*)d_in[1];
    const float* Whh  = (const float*)d_in[2];
    const float* bih  = (const float*)d_in[3];
    const float* bhh  = (const float*)d_in[4];
    const float* Wafc = (const float*)d_in[5];
    const float* bafc = (const float*)d_in[6];
    const float* Wao  = (const float*)d_in[7];
    const float* bao  = (const float*)d_in[8];
    const float* Wc   = (const float*)d_in[9];
    const float* bc   = (const float*)d_in[10];
    const float* Wb   = (const float*)d_in[11];
    const float* bb   = (const float*)d_in[12];
    float* out = (float*)d_out;

    cudaFuncSetAttribute(kB,  cudaFuncAttributeMaxDynamicSharedMemorySize, SMEM_B);
    cudaFuncSetAttribute(kC1, cudaFuncAttributeMaxDynamicSharedMemorySize, SMEM_C1);
    cudaFuncSetAttribute(kC2, cudaFuncAttributeMaxDynamicSharedMemorySize, SMEM_C2);

    k_init<<<4, 256>>>();
    kA<<<dim3(4, 32, 128), 256>>>(x, Wih, bih, bhh);
    kB<<<128, 512, SMEM_B>>>(Whh);
    kC1<<<4096, 256, SMEM_C1>>>(Wafc, bafc);
    kC2<<<4096, 256, SMEM_C2>>>(x, Wao, bao, Wc, bc, Wb, bb, out);
}